// round 7
// baseline (speedup 1.0000x reference)
#include <cuda_runtime.h>
#include <cuda_bf16.h>
#include <math.h>
#include <stdint.h>

#define BATCH 4
#define SEQ   2048
#define EMB   1024
#define HID   1024
#define MTOT  (BATCH * SEQ)

// ---------------------------------------------------------------------------
// Device-global scratch
// ---------------------------------------------------------------------------
__device__ __nv_bfloat16 g_xh[MTOT * EMB], g_xl[MTOT * EMB];
__device__ __nv_bfloat16 g_wh[3 * HID * EMB], g_wl[3 * HID * EMB];
__device__ __nv_bfloat16 g_qh[MTOT * HID], g_ql[MTOT * HID];
__device__ __nv_bfloat16 g_kh[MTOT * HID], g_kl[MTOT * HID];
__device__ __nv_bfloat16 g_vth[BATCH * HID * SEQ], g_vtl[BATCH * HID * SEQ];
__device__ __nv_bfloat16 g_ah[(size_t)BATCH * SEQ * SEQ];
__device__ __nv_bfloat16 g_al[(size_t)BATCH * SEQ * SEQ];
__device__ float         g_sum[MTOT];   // per-row softmax denominator (atomics)

// ---------------------------------------------------------------------------
// Helpers
// ---------------------------------------------------------------------------
__device__ __forceinline__ uint32_t smem_u32(const void* p) {
    uint32_t a;
    asm("{ .reg .u64 t; cvta.to.shared.u64 t, %1; cvt.u32.u64 %0, t; }"
        : "=r"(a) : "l"(p));
    return a;
}

__device__ __forceinline__ uint32_t pack2(__nv_bfloat16 a, __nv_bfloat16 b) {
    __nv_bfloat162 t = __halves2bfloat162(a, b);
    return *reinterpret_cast<uint32_t*>(&t);
}

__device__ __forceinline__ void split1(float v, __nv_bfloat16& h, __nv_bfloat16& l) {
    h = __float2bfloat16_rn(v);
    l = __float2bfloat16_rn(v - __bfloat162float(h));
}

// FMA-pipe exp (degree-6 2^f poly, rel err ~1.2e-7); avoids the MUFU path.
__device__ __forceinline__ float fexp(float x) {
    x = fminf(fmaxf(x, -87.f), 87.f);
    const float t = x * 1.4426950408889634f;
    const int i = __float2int_rn(t);
    const float f = t - (float)i;
    float p = 1.54035304e-4f;
    p = fmaf(p, f, 1.33335581e-3f);
    p = fmaf(p, f, 9.61812910e-3f);
    p = fmaf(p, f, 5.55041086e-2f);
    p = fmaf(p, f, 2.40226462e-1f);
    p = fmaf(p, f, 6.93147182e-1f);
    p = fmaf(p, f, 1.0f);
    return p * __int_as_float((i + 127) << 23);
}

#define CP16(dst, src)                                                         \
    asm volatile("cp.async.cg.shared.global [%0], [%1], 16;" ::"r"(dst),       \
                 "l"(src))
#define CP_COMMIT() asm volatile("cp.async.commit_group;" ::: "memory")
#define CP_WAIT1()  asm volatile("cp.async.wait_group 1;" ::: "memory")

__device__ __forceinline__ void ldsm4(uint32_t* r, uint32_t addr) {
    asm volatile(
        "ldmatrix.sync.aligned.m8n8.x4.shared.b16 {%0,%1,%2,%3}, [%4];"
        : "=r"(r[0]), "=r"(r[1]), "=r"(r[2]), "=r"(r[3])
        : "r"(addr));
}

__device__ __forceinline__ void mma_bf16(float* c, const uint32_t* a,
                                         uint32_t b0, uint32_t b1) {
    asm volatile(
        "mma.sync.aligned.m16n8k16.row.col.f32.bf16.bf16.f32 "
        "{%0,%1,%2,%3}, {%4,%5,%6,%7}, {%8,%9}, {%0,%1,%2,%3};"
        : "+f"(c[0]), "+f"(c[1]), "+f"(c[2]), "+f"(c[3])
        : "r"(a[0]), "r"(a[1]), "r"(a[2]), "r"(a[3]), "r"(b0), "r"(b1));
}

// Swizzled byte offset inside a 128x32 bf16 tile (rows of 64B = 4x16B units)
__device__ __forceinline__ uint32_t swz(int row, int unit) {
    return (uint32_t)(row * 64 + ((unit ^ ((row >> 1) & 3)) << 4));
}

// ---------------------------------------------------------------------------
// bf16x3 emulated-fp32 GEMM via mma.sync (NT): D[m,n] = sum_k A[m,k]*B[n,k]
// MODE 0: fused QKV projection (z: 0=Q, 1=K, 2=V transposed-in-epilogue)
// MODE 2: scores -> fused causal mask + exp + row-sum atomics; writes
//         UNNORMALIZED e as bf16 hi/lo (triangular grid decode)
// MODE 3: attn @ V^T; per-row 1/sum normalization in epilogue
// ---------------------------------------------------------------------------
#define BKC 32
#define STAGES 3
#define STAGE_BYTES (4 * 128 * BKC * 2)
#define GEMM_SMEM (STAGES * STAGE_BYTES)
#define OFF_AH 0
#define OFF_AL (128 * BKC * 2)
#define OFF_BH (2 * 128 * BKC * 2)
#define OFF_BL (3 * 128 * BKC * 2)

template <int MODE>
__global__ __launch_bounds__(256, 2)
void gemm_tc(const __nv_bfloat16* __restrict__ Ah, const __nv_bfloat16* __restrict__ Al,
             const __nv_bfloat16* __restrict__ Bh, const __nv_bfloat16* __restrict__ Bl,
             const float* __restrict__ bias_q, const float* __restrict__ bias_k,
             const float* __restrict__ bias_v,
             float* __restrict__ Cf,
             __nv_bfloat16* __restrict__ Chi, __nv_bfloat16* __restrict__ Clo,
             __nv_bfloat16* __restrict__ Chi2, __nv_bfloat16* __restrict__ Clo2,
             __nv_bfloat16* __restrict__ Vth, __nv_bfloat16* __restrict__ Vtl,
             float* __restrict__ sump,
             int K, int lda, int ldb, int ldc,
             size_t strA, size_t strB, size_t strC, float scale) {
    int bm, bn;
    if (MODE == 2) {
        // triangular decode: blockIdx.x in [0,136) -> (bm, bn<=bm)
        const int i = blockIdx.x;
        int t = (int)((sqrtf(8.f * i + 1.f) - 1.f) * 0.5f);
        while ((t + 1) * (t + 2) / 2 <= i) t++;
        while (t * (t + 1) / 2 > i) t--;
        bm = t;
        bn = i - t * (t + 1) / 2;
    } else {
        bn = blockIdx.x;
        bm = (MODE == 0) ? blockIdx.y : (gridDim.y - 1 - blockIdx.y);
    }
    const int bz = blockIdx.z;

    extern __shared__ __align__(1024) char smem[];
    const uint32_t sb = smem_u32(smem);

    const int tid = threadIdx.x;
    const int wid = tid >> 5, lane = tid & 31;

    const __nv_bfloat16* pAh = Ah + strA * bz + (size_t)bm * 128 * lda;
    const __nv_bfloat16* pAl = Al + strA * bz + (size_t)bm * 128 * lda;
    const __nv_bfloat16* pBh = Bh + strB * bz + (size_t)bn * 128 * ldb;
    const __nv_bfloat16* pBl = Bl + strB * bz + (size_t)bn * 128 * ldb;

    int nch = K / BKC;
    if (MODE == 3) nch = 4 * (bm + 1);  // causal truncation

    const int fr0 = tid >> 2, fu0 = tid & 3;
    const int fr1 = (tid + 256) >> 2, fu1 = tid & 3;

    auto fill = [&](int stage, int ck) {
        const uint32_t base = sb + stage * STAGE_BYTES;
        const int k0 = ck * BKC;
        {
            const uint32_t o = swz(fr0, fu0);
            const size_t ga = (size_t)fr0 * lda + k0 + fu0 * 8;
            const size_t gb = (size_t)fr0 * ldb + k0 + fu0 * 8;
            CP16(base + OFF_AH + o, pAh + ga);
            CP16(base + OFF_AL + o, pAl + ga);
            CP16(base + OFF_BH + o, pBh + gb);
            CP16(base + OFF_BL + o, pBl + gb);
        }
        {
            const uint32_t o = swz(fr1, fu1);
            const size_t ga = (size_t)fr1 * lda + k0 + fu1 * 8;
            const size_t gb = (size_t)fr1 * ldb + k0 + fu1 * 8;
            CP16(base + OFF_AH + o, pAh + ga);
            CP16(base + OFF_AL + o, pAl + ga);
            CP16(base + OFF_BH + o, pBh + gb);
            CP16(base + OFF_BL + o, pBl + gb);
        }
    };

    const int wm = wid >> 1;
    const int wn = (wid & 1) * 64;
    const int wr = wm * 32;

    float acc[2][8][4];
#pragma unroll
    for (int i = 0; i < 2; i++)
#pragma unroll
        for (int j = 0; j < 8; j++)
#pragma unroll
            for (int t = 0; t < 4; t++) acc[i][j][t] = 0.f;

    const int a_row = (lane & 15);
    const int a_ukx = (lane >> 4);
    const int b_row = ((lane >> 4) & 1) * 8 + (lane & 7);
    const int b_ukx = ((lane >> 3) & 1);

    fill(0, 0); CP_COMMIT();
    fill(1, 1); CP_COMMIT();

    for (int ck = 0; ck < nch; ck++) {
        CP_WAIT1();
        __syncthreads();
        if (ck + 2 < nch) fill((ck + 2) % STAGES, ck + 2);
        CP_COMMIT();

        const uint32_t base = sb + (ck % STAGES) * STAGE_BYTES;

#pragma unroll
        for (int ks = 0; ks < 2; ks++) {
            uint32_t ahf[2][4], alf[2][4];
#pragma unroll
            for (int mi = 0; mi < 2; mi++) {
                const uint32_t addr =
                    base + swz(wr + mi * 16 + a_row, 2 * ks + a_ukx);
                ldsm4(ahf[mi], OFF_AH + addr);
                ldsm4(alf[mi], OFF_AL + addr);
            }
            uint32_t bhf[2][4], blf[2][4];
            {
                const uint32_t a0 = base + swz(wn + b_row, 2 * ks + b_ukx);
                ldsm4(bhf[0], OFF_BH + a0);
                ldsm4(blf[0], OFF_BL + a0);
            }
#pragma unroll
            for (int np = 0; np < 4; np++) {
                const int cur = np & 1;
                if (np < 3) {
                    const uint32_t a1 =
                        base + swz(wn + (np + 1) * 16 + b_row, 2 * ks + b_ukx);
                    ldsm4(bhf[cur ^ 1], OFF_BH + a1);
                    ldsm4(blf[cur ^ 1], OFF_BL + a1);
                }
#pragma unroll
                for (int mi = 0; mi < 2; mi++) {
                    mma_bf16(acc[mi][np * 2 + 0], ahf[mi], bhf[cur][0], bhf[cur][1]);
                    mma_bf16(acc[mi][np * 2 + 0], ahf[mi], blf[cur][0], blf[cur][1]);
                    mma_bf16(acc[mi][np * 2 + 0], alf[mi], bhf[cur][0], bhf[cur][1]);
                    mma_bf16(acc[mi][np * 2 + 1], ahf[mi], bhf[cur][2], bhf[cur][3]);
                    mma_bf16(acc[mi][np * 2 + 1], ahf[mi], blf[cur][2], blf[cur][3]);
                    mma_bf16(acc[mi][np * 2 + 1], alf[mi], bhf[cur][2], bhf[cur][3]);
                }
            }
        }
    }

    // ---------------- epilogue ----------------
    if (MODE == 0 && bz == 2) {
        __syncthreads();
        float* ts = (float*)smem;  // [128 cols][132 rows]
        const int lr = wr + (lane >> 2);
        const int lc = wn + ((lane & 3) << 1);
#pragma unroll
        for (int mi = 0; mi < 2; mi++) {
#pragma unroll
            for (int nb = 0; nb < 8; nb++) {
                const float* c = acc[mi][nb];
                const int col = lc + nb * 8;
                const int r0 = lr + mi * 16;
                const float2 b2 = *(const float2*)(bias_v + bn * 128 + col);
                ts[col * 132 + r0]           = c[0] + b2.x;
                ts[(col + 1) * 132 + r0]     = c[1] + b2.y;
                ts[col * 132 + r0 + 8]       = c[2] + b2.x;
                ts[(col + 1) * 132 + r0 + 8] = c[3] + b2.y;
            }
        }
        __syncthreads();
        const int m0 = bm * 128;
        const int b = m0 >> 11;
        const int s0 = m0 & (SEQ - 1);
        const size_t obase = (size_t)b * HID * SEQ + (size_t)(bn * 128) * SEQ + s0;
#pragma unroll
        for (int it = 0; it < 32; it++) {
            const int i2 = it * 256 + tid;
            const int h = i2 >> 6;
            const int sp = (i2 & 63) << 1;
            const float2 v = *(const float2*)&ts[h * 132 + sp];
            __nv_bfloat16 h0, l0, h1, l1;
            split1(v.x, h0, l0);
            split1(v.y, h1, l1);
            const size_t o = obase + (size_t)h * SEQ + sp;
            *(uint32_t*)(Vth + o) = pack2(h0, h1);
            *(uint32_t*)(Vtl + o) = pack2(l0, l1);
        }
        return;
    }

    const int rb = bm * 128 + wr + (lane >> 2);
    const int cb = bn * 128 + wn + ((lane & 3) << 1);

    if (MODE == 2) {
        // fused causal mask + exp + unnormalized-e store + row-sum atomics
        float rs[2][2] = {{0.f, 0.f}, {0.f, 0.f}};
#pragma unroll
        for (int mi = 0; mi < 2; mi++) {
#pragma unroll
            for (int nb = 0; nb < 8; nb++) {
                const float* c = acc[mi][nb];
                const int r0 = rb + mi * 16;
                const int r1 = r0 + 8;
                const int col = cb + nb * 8;
                const float e0 = (col     <= r0) ? fexp(c[0] * scale) : 0.f;
                const float e1 = (col + 1 <= r0) ? fexp(c[1] * scale) : 0.f;
                const float e2 = (col     <= r1) ? fexp(c[2] * scale) : 0.f;
                const float e3 = (col + 1 <= r1) ? fexp(c[3] * scale) : 0.f;
                rs[mi][0] += e0 + e1;
                rs[mi][1] += e2 + e3;
                __nv_bfloat16 h0, l0, h1, l1;
                split1(e0, h0, l0); split1(e1, h1, l1);
                const size_t o0 = strC * bz + (size_t)r0 * ldc + col;
                *(uint32_t*)(Chi + o0) = pack2(h0, h1);
                *(uint32_t*)(Clo + o0) = pack2(l0, l1);
                split1(e2, h0, l0); split1(e3, h1, l1);
                const size_t o1 = strC * bz + (size_t)r1 * ldc + col;
                *(uint32_t*)(Chi + o1) = pack2(h0, h1);
                *(uint32_t*)(Clo + o1) = pack2(l0, l1);
            }
        }
        // reduce across the 4 lanes of each quad (same row)
#pragma unroll
        for (int mi = 0; mi < 2; mi++) {
#pragma unroll
            for (int j = 0; j < 2; j++) {
                rs[mi][j] += __shfl_xor_sync(0xffffffffu, rs[mi][j], 1);
                rs[mi][j] += __shfl_xor_sync(0xffffffffu, rs[mi][j], 2);
            }
        }
        if ((lane & 3) == 0) {
#pragma unroll
            for (int mi = 0; mi < 2; mi++) {
#pragma unroll
                for (int j = 0; j < 2; j++) {
                    const int row = rb + mi * 16 + j * 8;
                    atomicAdd(&sump[bz * SEQ + row], rs[mi][j]);
                }
            }
        }
        return;
    }

#pragma unroll
    for (int mi = 0; mi < 2; mi++) {
        if (MODE == 3) {
            const int r0 = rb + mi * 16;
            const float is0 = 1.0f / sump[bz * SEQ + r0];
            const float is1 = 1.0f / sump[bz * SEQ + r0 + 8];
#pragma unroll
            for (int nb = 0; nb < 8; nb++) {
                const float* c = acc[mi][nb];
                const int col = cb + nb * 8;
                float* dst = Cf + strC * bz;
                *(float2*)(dst + (size_t)r0 * ldc + col) =
                    make_float2(c[0] * is0, c[1] * is0);
                *(float2*)(dst + (size_t)(r0 + 8) * ldc + col) =
                    make_float2(c[2] * is1, c[3] * is1);
            }
        } else {  // MODE 0, bz 0/1
#pragma unroll
            for (int nb = 0; nb < 8; nb++) {
                const float* c = acc[mi][nb];
                const int r0 = rb + mi * 16;
                const int col = cb + nb * 8;
                const float* bias = (bz == 0) ? bias_q : bias_k;
                const float2 b2 = *(const float2*)(bias + col);
                __nv_bfloat16* oh = (bz == 0) ? Chi : Chi2;
                __nv_bfloat16* ol = (bz == 0) ? Clo : Clo2;
                __nv_bfloat16 h0, l0, h1, l1;
                split1(c[0] + b2.x, h0, l0);
                split1(c[1] + b2.y, h1, l1);
                *(uint32_t*)(oh + (size_t)r0 * ldc + col) = pack2(h0, h1);
                *(uint32_t*)(ol + (size_t)r0 * ldc + col) = pack2(l0, l1);
                split1(c[2] + b2.x, h0, l0);
                split1(c[3] + b2.y, h1, l1);
                *(uint32_t*)(oh + (size_t)(r0 + 8) * ldc + col) = pack2(h0, h1);
                *(uint32_t*)(ol + (size_t)(r0 + 8) * ldc + col) = pack2(l0, l1);
            }
        }
    }
}

// ---------------------------------------------------------------------------
// fp32 -> (bf16 hi, bf16 lo) split; z selects one of up to 3 sources
// ---------------------------------------------------------------------------
__global__ __launch_bounds__(256)
void split_f32x3(const float4* __restrict__ s0, const float4* __restrict__ s1,
                 const float4* __restrict__ s2,
                 uint2* __restrict__ hi, uint2* __restrict__ lo, int n4) {
    const int i = blockIdx.x * 256 + threadIdx.x;
    if (i >= n4) return;
    const int z = blockIdx.z;
    const float4* src = (z == 0) ? s0 : (z == 1) ? s1 : s2;
    float4 v = src[i];
    const int o = z * n4 + i;
    __nv_bfloat16 h0, l0, h1, l1, h2, l2, h3, l3;
    split1(v.x, h0, l0); split1(v.y, h1, l1);
    split1(v.z, h2, l2); split1(v.w, h3, l3);
    hi[o] = make_uint2(pack2(h0, h1), pack2(h2, h3));
    lo[o] = make_uint2(pack2(l0, l1), pack2(l2, l3));
}

// ---------------------------------------------------------------------------
extern "C" void kernel_launch(void* const* d_in, const int* in_sizes, int n_in,
                              void* d_out, int out_size) {
    const float* x  = (const float*)d_in[0];
    const float* Wq = (const float*)d_in[1];
    const float* bq = (const float*)d_in[2];
    const float* Wk = (const float*)d_in[3];
    const float* bk = (const float*)d_in[4];
    const float* Wv = (const float*)d_in[5];
    const float* bv = (const float*)d_in[6];
    float* out = (float*)d_out;

    __nv_bfloat16 *xh, *xl, *wh, *wl, *qh, *ql, *kh, *kl, *vth, *vtl, *ah, *al;
    float *sum;
    cudaGetSymbolAddress((void**)&xh, g_xh);   cudaGetSymbolAddress((void**)&xl, g_xl);
    cudaGetSymbolAddress((void**)&wh, g_wh);   cudaGetSymbolAddress((void**)&wl, g_wl);
    cudaGetSymbolAddress((void**)&qh, g_qh);   cudaGetSymbolAddress((void**)&ql, g_ql);
    cudaGetSymbolAddress((void**)&kh, g_kh);   cudaGetSymbolAddress((void**)&kl, g_kl);
    cudaGetSymbolAddress((void**)&vth, g_vth); cudaGetSymbolAddress((void**)&vtl, g_vtl);
    cudaGetSymbolAddress((void**)&ah, g_ah);   cudaGetSymbolAddress((void**)&al, g_al);
    cudaGetSymbolAddress((void**)&sum, g_sum);

    cudaFuncSetAttribute(gemm_tc<0>, cudaFuncAttributeMaxDynamicSharedMemorySize, GEMM_SMEM);
    cudaFuncSetAttribute(gemm_tc<2>, cudaFuncAttributeMaxDynamicSharedMemorySize, GEMM_SMEM);
    cudaFuncSetAttribute(gemm_tc<3>, cudaFuncAttributeMaxDynamicSharedMemorySize, GEMM_SMEM);

    // 0) zero softmax denominators (graph-capturable memset node)
    cudaMemsetAsync(sum, 0, MTOT * sizeof(float));

    // 1) split input + weights into bf16 hi/lo
    split_f32x3<<<dim3(MTOT * EMB / 4 / 256, 1, 1), 256>>>(
        (const float4*)x, nullptr, nullptr, (uint2*)xh, (uint2*)xl, MTOT * EMB / 4);
    const int wn4 = HID * EMB / 4;
    split_f32x3<<<dim3(wn4 / 256, 1, 3), 256>>>(
        (const float4*)Wq, (const float4*)Wk, (const float4*)Wv,
        (uint2*)wh, (uint2*)wl, wn4);

    // 2) fused Q/K/V projections (V transposed in-epilogue)
    dim3 gq(HID / 128, MTOT / 128, 3);
    gemm_tc<0><<<gq, 256, GEMM_SMEM>>>(xh, xl, wh, wl, bq, bk, bv,
                                       nullptr, qh, ql, kh, kl, vth, vtl, nullptr,
                                       EMB, EMB, EMB, HID,
                                       0, (size_t)HID * EMB, 0, 1.f);

    // 3) scores + fused mask/exp/row-sum -> unnormalized e (bf16 hi/lo)
    dim3 gs(SEQ / 128 * (SEQ / 128 + 1) / 2, 1, BATCH);  // (136, 1, 4)
    gemm_tc<2><<<gs, 256, GEMM_SMEM>>>(qh, ql, kh, kl, nullptr, nullptr, nullptr,
                                       nullptr, ah, al, nullptr, nullptr,
                                       nullptr, nullptr, sum,
                                       HID, HID, HID, SEQ,
                                       (size_t)SEQ * HID, (size_t)SEQ * HID,
                                       (size_t)SEQ * SEQ, 0.03125f);

    // 4) out = (e @ V^T) / sum[row]  (heavy rows first)
    dim3 ga(HID / 128, SEQ / 128, BATCH);
    gemm_tc<3><<<ga, 256, GEMM_SMEM>>>(ah, al, vth, vtl, nullptr, nullptr, nullptr,
                                       out, nullptr, nullptr, nullptr, nullptr,
                                       nullptr, nullptr, sum,
                                       SEQ, SEQ, SEQ, HID,
                                       (size_t)SEQ * SEQ, (size_t)HID * SEQ,
                                       (size_t)SEQ * HID, 1.f);
}